// round 14
// baseline (speedup 1.0000x reference)
#include <cuda_runtime.h>
#include <cuda_bf16.h>
#include <math.h>

#define B_SZ   16
#define C_IN   64
#define HH     256
#define WW     256
#define CKK    576
#define FC_DIM 512
#define IMG_PIX (HH * WW)
#define N_IMG  (B_SZ * C_IN)
#define FOUT_ELEMS ((size_t)N_IMG * IMG_PIX)

#define MLP2_BLOCKS 27   // 3 j-tiles x 9 i-chunks; all co-resident

// Partials (deterministic fixed-order summation)
__device__ float g_p1[8][B_SZ * CKK];   // layer1 partials per 64-i-chunk (ic0 includes b1)
__device__ float g_p2[9][B_SZ * CKK];   // layer2 partials per 64-i-chunk (ic0 includes b2)
__device__ float g_kw[B_SZ * CKK];      // softmaxed kernel weights

// Padded counters (own 128B line each; zero-init; self-resetting)
struct __align__(128) PadCtr { unsigned int v; unsigned int pad[31]; };
__device__ PadCtr g_cb;   // mlp2 barrier counter
__device__ PadCtr g_ce;   // mlp2 exit counter

// ---------------------------------------------------------------------------
// Layer 1: 24 blocks = (jt 0..2) x (ic 0..7). Block: 192 threads.
// Stage W1 tile [64 x 192] (float4, read once grid-wide) + Fc slice [16 x 64].
// ---------------------------------------------------------------------------
__global__ __launch_bounds__(192) void EKG_mlp1(
    const float* __restrict__ Fc,
    const float* __restrict__ W1, const float* __restrict__ b1)
{
    __shared__ float sw[64 * 192];    // 48KB weight tile
    __shared__ float sfc[16 * 64];    // 4KB input slice

    const int jt = blockIdx.x;        // 0..2
    const int ic = blockIdx.y;        // 0..7
    const int i0 = ic * 64;
    const int tid = threadIdx.x;
    const int j  = jt * 192 + tid;

    {
        const float4* __restrict__ W1_4 = (const float4*)W1;
        float4* sw4 = (float4*)sw;
        #pragma unroll
        for (int q = tid; q < 64 * 48; q += 192) {
            const int r = q / 48, c = q % 48;
            sw4[r * 48 + c] = __ldg(W1_4 + (size_t)(i0 + r) * (CKK / 4) + jt * 48 + c);
        }
    }
    {
        const float4* __restrict__ Fc4 = (const float4*)Fc;
        float4* sfc4 = (float4*)sfc;
        #pragma unroll
        for (int q = tid; q < 256; q += 192) {
            const int b = q >> 4, c = q & 15;
            sfc4[b * 16 + c] = __ldg(Fc4 + b * (FC_DIM / 4) + ic * 16 + c);
        }
    }
    __syncthreads();

    float acc[16];
    #pragma unroll
    for (int b = 0; b < 16; ++b) acc[b] = 0.f;
    #pragma unroll 4
    for (int il = 0; il < 64; ++il) {
        const float w = sw[il * 192 + tid];
        #pragma unroll
        for (int b = 0; b < 16; ++b)
            acc[b] = fmaf(sfc[b * 64 + il], w, acc[b]);
    }

    const float bias = (ic == 0) ? b1[j] : 0.0f;
    #pragma unroll
    for (int b = 0; b < 16; ++b)
        g_p1[ic][b * CKK + j] = acc[b] + bias;
}

// ---------------------------------------------------------------------------
// Layer 2 + fused softmax: 27 blocks = (jt 0..2) x (ic 0..8), 192 threads.
// After all 27 blocks publish g_p2 partials (spin barrier), blocks with
// linear id < 16 run the softmax for batch id.
// ---------------------------------------------------------------------------
__global__ __launch_bounds__(192) void EKG_mlp2_sm(
    const float* __restrict__ W2, const float* __restrict__ b2,
    float* __restrict__ kw_tail, int write_tail)
{
    __shared__ float sw[64 * 192];
    __shared__ float sfc[16 * 64];
    __shared__ float red[8];
    __shared__ float bcast;

    const int jt = blockIdx.x;        // 0..2
    const int ic = blockIdx.y;        // 0..8
    const int i0 = ic * 64;
    const int tid = threadIdx.x;
    const int j  = jt * 192 + tid;
    const int lin = blockIdx.y * 3 + blockIdx.x;   // 0..26
    const int lane = tid & 31;
    const int wid  = tid >> 5;        // 0..5

    {
        const float4* __restrict__ W2_4 = (const float4*)W2;
        float4* sw4 = (float4*)sw;
        #pragma unroll
        for (int q = tid; q < 64 * 48; q += 192) {
            const int r = q / 48, c = q % 48;
            sw4[r * 48 + c] = __ldg(W2_4 + (size_t)(i0 + r) * (CKK / 4) + jt * 48 + c);
        }
    }
    #pragma unroll
    for (int q = tid; q < 1024; q += 192) {
        const int b = q >> 6, il = q & 63;
        const int idx = b * CKK + i0 + il;
        float h = (((g_p1[0][idx] + g_p1[1][idx]) + (g_p1[2][idx] + g_p1[3][idx])) +
                   ((g_p1[4][idx] + g_p1[5][idx]) + (g_p1[6][idx] + g_p1[7][idx])));
        sfc[q] = fmaxf(h, 0.0f);
    }
    __syncthreads();

    float acc[16];
    #pragma unroll
    for (int b = 0; b < 16; ++b) acc[b] = 0.f;
    #pragma unroll 4
    for (int il = 0; il < 64; ++il) {
        const float w = sw[il * 192 + tid];
        #pragma unroll
        for (int b = 0; b < 16; ++b)
            acc[b] = fmaf(sfc[b * 64 + il], w, acc[b]);
    }

    const float bias = (ic == 0) ? b2[j] : 0.0f;
    #pragma unroll
    for (int b = 0; b < 16; ++b)
        g_p2[ic][b * CKK + j] = acc[b] + bias;

    // ---- spin barrier over the 27 blocks ----
    __threadfence();
    __syncthreads();
    if (tid == 0) {
        atomicAdd(&g_cb.v, 1u);
        while (__ldcg(&g_cb.v) < MLP2_BLOCKS) __nanosleep(20);
    }
    __syncthreads();
    __threadfence();

    // ---- softmax: blocks 0..15 handle batch lin ----
    if (lin < B_SZ) {
        const int b = lin;
        float lg[3];
        float lmax = -INFINITY;
        #pragma unroll
        for (int t = 0; t < 3; ++t) {
            const int idx = b * CKK + tid + 192 * t;
            float v = ((((g_p2[0][idx] + g_p2[1][idx]) + (g_p2[2][idx] + g_p2[3][idx])) +
                        ((g_p2[4][idx] + g_p2[5][idx]) + (g_p2[6][idx] + g_p2[7][idx]))) +
                       g_p2[8][idx]);
            lg[t] = v;
            lmax = fmaxf(lmax, v);
        }
        #pragma unroll
        for (int o = 16; o > 0; o >>= 1)
            lmax = fmaxf(lmax, __shfl_xor_sync(0xffffffffu, lmax, o));
        if (lane == 0) red[wid] = lmax;
        __syncthreads();
        if (wid == 0) {
            float v = (lane < 6) ? red[lane] : -INFINITY;
            #pragma unroll
            for (int o = 4; o > 0; o >>= 1)
                v = fmaxf(v, __shfl_xor_sync(0xffffffffu, v, o));
            if (lane == 0) bcast = v;
        }
        __syncthreads();
        const float maxv = bcast;

        float e[3];
        float lsum = 0.f;
        #pragma unroll
        for (int t = 0; t < 3; ++t) { e[t] = expf(lg[t] - maxv); lsum += e[t]; }
        #pragma unroll
        for (int o = 16; o > 0; o >>= 1)
            lsum += __shfl_xor_sync(0xffffffffu, lsum, o);
        __syncthreads();
        if (lane == 0) red[wid] = lsum;
        __syncthreads();
        if (wid == 0) {
            float v = (lane < 6) ? red[lane] : 0.0f;
            #pragma unroll
            for (int o = 4; o > 0; o >>= 1)
                v += __shfl_xor_sync(0xffffffffu, v, o);
            if (lane == 0) bcast = v;
        }
        __syncthreads();
        const float inv = 1.0f / bcast;

        #pragma unroll
        for (int t = 0; t < 3; ++t) {
            const int idx = b * CKK + tid + 192 * t;
            const float kw = e[t] * inv;
            g_kw[idx] = kw;
            if (write_tail) kw_tail[idx] = kw;
        }
    }

    // exit barrier: last arriver resets both counters for graph replay
    __threadfence();
    __syncthreads();
    if (tid == 0) {
        unsigned int old = atomicAdd(&g_ce.v, 1u);
        if (old == MLP2_BLOCKS - 1u) { g_cb.v = 0u; g_ce.v = 0u; __threadfence(); }
    }
}

// ---------------------------------------------------------------------------
// Depthwise 3x3 conv, reflect pad, no smem (measured-best, unchanged).
// Block 256: tx 0..63 (float4 col group), ty 0..3 (8-row strip). Grid (8,1024).
// ---------------------------------------------------------------------------
#define ROWS_PER_BLOCK 32
#define ROWS_PER_THREAD 8

__device__ __forceinline__ void load_row6(
    const float* __restrict__ img, int gr, int tx, float* __restrict__ w)
{
    gr = (gr < 0) ? 1 : ((gr > HH - 1) ? (2 * HH - 2 - gr) : gr);
    const float* rowp = img + gr * WW;
    const float4 q = __ldg((const float4*)rowp + tx);
    w[1] = q.x; w[2] = q.y; w[3] = q.z; w[4] = q.w;
    w[0] = (tx == 0)      ? q.y : __ldg(rowp + 4 * tx - 1);
    w[5] = (tx == WW/4-1) ? q.z : __ldg(rowp + 4 * tx + 4);
}

__global__ __launch_bounds__(256) void EKG_conv_kernel(
    const float* __restrict__ Fd,
    float* __restrict__ out)
{
    const int bc   = blockIdx.y;
    const int tid  = threadIdx.x;
    const int tx   = tid & 63;
    const int ty   = tid >> 6;
    const int rbase = blockIdx.x * ROWS_PER_BLOCK + ty * ROWS_PER_THREAD;

    const float* __restrict__ img = Fd  + (size_t)bc * IMG_PIX;
    float*       __restrict__ o   = out + (size_t)bc * IMG_PIX;

    const float* kwp = g_kw + bc * 9;
    const float w00 = __ldg(kwp+0), w01 = __ldg(kwp+1), w02 = __ldg(kwp+2);
    const float w10 = __ldg(kwp+3), w11 = __ldg(kwp+4), w12 = __ldg(kwp+5);
    const float w20 = __ldg(kwp+6), w21 = __ldg(kwp+7), w22 = __ldg(kwp+8);

    float win[3][6];
    load_row6(img, rbase - 1, tx, win[0]);
    load_row6(img, rbase + 0, tx, win[1]);

    #pragma unroll
    for (int rr = 0; rr < ROWS_PER_THREAD; ++rr) {
        load_row6(img, rbase + rr + 1, tx, win[(rr + 2) % 3]);

        const float* T  = win[rr % 3];
        const float* M  = win[(rr + 1) % 3];
        const float* Bt = win[(rr + 2) % 3];

        float4 r;
        r.x = w00*T[0]; r.x = fmaf(w01,T[1],r.x); r.x = fmaf(w02,T[2],r.x);
        r.x = fmaf(w10,M[0],r.x); r.x = fmaf(w11,M[1],r.x); r.x = fmaf(w12,M[2],r.x);
        r.x = fmaf(w20,Bt[0],r.x); r.x = fmaf(w21,Bt[1],r.x); r.x = fmaf(w22,Bt[2],r.x);

        r.y = w00*T[1]; r.y = fmaf(w01,T[2],r.y); r.y = fmaf(w02,T[3],r.y);
        r.y = fmaf(w10,M[1],r.y); r.y = fmaf(w11,M[2],r.y); r.y = fmaf(w12,M[3],r.y);
        r.y = fmaf(w20,Bt[1],r.y); r.y = fmaf(w21,Bt[2],r.y); r.y = fmaf(w22,Bt[3],r.y);

        r.z = w00*T[2]; r.z = fmaf(w01,T[3],r.z); r.z = fmaf(w02,T[4],r.z);
        r.z = fmaf(w10,M[2],r.z); r.z = fmaf(w11,M[3],r.z); r.z = fmaf(w12,M[4],r.z);
        r.z = fmaf(w20,Bt[2],r.z); r.z = fmaf(w21,Bt[3],r.z); r.z = fmaf(w22,Bt[4],r.z);

        r.w = w00*T[3]; r.w = fmaf(w01,T[4],r.w); r.w = fmaf(w02,T[5],r.w);
        r.w = fmaf(w10,M[3],r.w); r.w = fmaf(w11,M[4],r.w); r.w = fmaf(w12,M[5],r.w);
        r.w = fmaf(w20,Bt[3],r.w); r.w = fmaf(w21,Bt[4],r.w); r.w = fmaf(w22,Bt[5],r.w);

        __stcs((float4*)(o + (size_t)(rbase + rr) * WW + 4 * tx), r);
    }
}

// ---------------------------------------------------------------------------
extern "C" void kernel_launch(void* const* d_in, const int* in_sizes, int n_in,
                              void* d_out, int out_size) {
    const float* Fd = (const float*)d_in[0];
    const float* Fc = (const float*)d_in[1];
    const float* W1 = (const float*)d_in[2];
    const float* b1 = (const float*)d_in[3];
    const float* W2 = (const float*)d_in[4];
    const float* b2 = (const float*)d_in[5];
    float* out = (float*)d_out;

    const int write_tail = ((size_t)out_size >= FOUT_ELEMS + (size_t)B_SZ * CKK) ? 1 : 0;
    float* kw_tail = out + FOUT_ELEMS;

    EKG_mlp1<<<dim3(3, 8), 192>>>(Fc, W1, b1);
    EKG_mlp2_sm<<<dim3(3, 9), 192>>>(W2, b2, kw_tail, write_tail);

    dim3 grid(HH / ROWS_PER_BLOCK, N_IMG);
    EKG_conv_kernel<<<grid, 256>>>(Fd, out);
}

// round 15
// speedup vs baseline: 1.2026x; 1.2026x over previous
#include <cuda_runtime.h>
#include <cuda_bf16.h>
#include <math.h>

#define B_SZ   16
#define C_IN   64
#define HH     256
#define WW     256
#define CKK    576
#define FC_DIM 512
#define IMG_PIX (HH * WW)
#define N_IMG  (B_SZ * C_IN)
#define FOUT_ELEMS ((size_t)N_IMG * IMG_PIX)

// Partials (deterministic fixed-order summation)
__device__ float g_p1[16][B_SZ * CKK];  // layer1 partials per 32-i-chunk (ic0 includes b1)
__device__ float g_p2[18][B_SZ * CKK];  // layer2 partials per 32-i-chunk (ic0 includes b2)
__device__ float g_kw[B_SZ * CKK];      // softmaxed kernel weights

// ---------------------------------------------------------------------------
// Layer 1: 48 blocks = (jt 0..2) x (ic 0..15). Block: 192 threads.
// Tile W1 [32 x 192] (24KB smem, 8 float4 loads/thread) + Fc slice [16 x 32].
// ---------------------------------------------------------------------------
__global__ __launch_bounds__(192) void EKG_mlp1(
    const float* __restrict__ Fc,
    const float* __restrict__ W1, const float* __restrict__ b1)
{
    __shared__ float sw[32 * 192];    // 24KB weight tile
    __shared__ float sfc[16 * 32];    // 2KB input slice

    const int jt = blockIdx.x;        // 0..2
    const int ic = blockIdx.y;        // 0..15
    const int i0 = ic * 32;
    const int tid = threadIdx.x;
    const int j  = jt * 192 + tid;

    {
        const float4* __restrict__ W1_4 = (const float4*)W1;
        float4* sw4 = (float4*)sw;
        #pragma unroll
        for (int q = tid; q < 32 * 48; q += 192) {
            const int r = q / 48, c = q % 48;
            sw4[r * 48 + c] = __ldg(W1_4 + (size_t)(i0 + r) * (CKK / 4) + jt * 48 + c);
        }
    }
    if (tid < 128) {
        const float4* __restrict__ Fc4 = (const float4*)Fc;
        float4* sfc4 = (float4*)sfc;
        const int b = tid >> 3, c = tid & 7;
        sfc4[b * 8 + c] = __ldg(Fc4 + b * (FC_DIM / 4) + ic * 8 + c);
    }
    __syncthreads();

    float acc[16];
    #pragma unroll
    for (int b = 0; b < 16; ++b) acc[b] = 0.f;
    #pragma unroll 4
    for (int il = 0; il < 32; ++il) {
        const float w = sw[il * 192 + tid];
        #pragma unroll
        for (int b = 0; b < 16; ++b)
            acc[b] = fmaf(sfc[b * 32 + il], w, acc[b]);
    }

    const float bias = (ic == 0) ? b1[j] : 0.0f;
    #pragma unroll
    for (int b = 0; b < 16; ++b)
        g_p1[ic][b * CKK + j] = acc[b] + bias;
}

// ---------------------------------------------------------------------------
// Layer 2: 54 blocks = (jt 0..2) x (ic 0..17). Same structure over W2.
// Input h = relu(sum of 16 layer-1 partials).
// ---------------------------------------------------------------------------
__global__ __launch_bounds__(192) void EKG_mlp2(
    const float* __restrict__ W2, const float* __restrict__ b2)
{
    __shared__ float sw[32 * 192];
    __shared__ float sfc[16 * 32];

    const int jt = blockIdx.x;        // 0..2
    const int ic = blockIdx.y;        // 0..17
    const int i0 = ic * 32;
    const int tid = threadIdx.x;
    const int j  = jt * 192 + tid;

    {
        const float4* __restrict__ W2_4 = (const float4*)W2;
        float4* sw4 = (float4*)sw;
        #pragma unroll
        for (int q = tid; q < 32 * 48; q += 192) {
            const int r = q / 48, c = q % 48;
            sw4[r * 48 + c] = __ldg(W2_4 + (size_t)(i0 + r) * (CKK / 4) + jt * 48 + c);
        }
    }
    // h slice [16 x 32] = relu(sum of 16 partials)
    #pragma unroll
    for (int q = tid; q < 512; q += 192) {
        const int b = q >> 5, il = q & 31;
        const int idx = b * CKK + i0 + il;
        float h = ((((g_p1[0][idx]  + g_p1[1][idx])  + (g_p1[2][idx]  + g_p1[3][idx])) +
                    ((g_p1[4][idx]  + g_p1[5][idx])  + (g_p1[6][idx]  + g_p1[7][idx]))) +
                   (((g_p1[8][idx]  + g_p1[9][idx])  + (g_p1[10][idx] + g_p1[11][idx])) +
                    ((g_p1[12][idx] + g_p1[13][idx]) + (g_p1[14][idx] + g_p1[15][idx]))));
        sfc[q] = fmaxf(h, 0.0f);
    }
    __syncthreads();

    float acc[16];
    #pragma unroll
    for (int b = 0; b < 16; ++b) acc[b] = 0.f;
    #pragma unroll 4
    for (int il = 0; il < 32; ++il) {
        const float w = sw[il * 192 + tid];
        #pragma unroll
        for (int b = 0; b < 16; ++b)
            acc[b] = fmaf(sfc[b * 32 + il], w, acc[b]);
    }

    const float bias = (ic == 0) ? b2[j] : 0.0f;
    #pragma unroll
    for (int b = 0; b < 16; ++b)
        g_p2[ic][b * CKK + j] = acc[b] + bias;
}

// ---------------------------------------------------------------------------
// Softmax over 576 (summing the 18 logit partials). grid 16, block 576.
// ---------------------------------------------------------------------------
__global__ __launch_bounds__(CKK) void EKG_softmax(
    float* __restrict__ kw_tail, int write_tail)
{
    __shared__ float red[32];
    __shared__ float bcast;
    const int b = blockIdx.x;
    const int j = threadIdx.x;
    const int lane = j & 31;
    const int wid  = j >> 5;
    const int idx  = b * CKK + j;

    float logit = 0.0f;
    #pragma unroll
    for (int t = 0; t < 18; ++t) logit += g_p2[t][idx];

    float m = logit;
    #pragma unroll
    for (int o = 16; o > 0; o >>= 1)
        m = fmaxf(m, __shfl_xor_sync(0xffffffffu, m, o));
    if (lane == 0) red[wid] = m;
    __syncthreads();
    if (wid == 0) {
        float v = (lane < 18) ? red[lane] : -INFINITY;
        #pragma unroll
        for (int o = 16; o > 0; o >>= 1)
            v = fmaxf(v, __shfl_xor_sync(0xffffffffu, v, o));
        if (lane == 0) bcast = v;
    }
    __syncthreads();
    const float e = expf(logit - bcast);

    float s = e;
    #pragma unroll
    for (int o = 16; o > 0; o >>= 1)
        s += __shfl_xor_sync(0xffffffffu, s, o);
    __syncthreads();
    if (lane == 0) red[wid] = s;
    __syncthreads();
    if (wid == 0) {
        float v = (lane < 18) ? red[lane] : 0.0f;
        #pragma unroll
        for (int o = 16; o > 0; o >>= 1)
            v += __shfl_xor_sync(0xffffffffu, v, o);
        if (lane == 0) bcast = v;
    }
    __syncthreads();

    const float kw = e / bcast;
    g_kw[idx] = kw;
    if (write_tail) kw_tail[idx] = kw;
}

// ---------------------------------------------------------------------------
// Depthwise 3x3 conv, reflect pad, no smem (measured-best, unchanged).
// Block 256: tx 0..63 (float4 col group), ty 0..3 (8-row strip). Grid (8,1024).
// ---------------------------------------------------------------------------
#define ROWS_PER_BLOCK 32
#define ROWS_PER_THREAD 8

__device__ __forceinline__ void load_row6(
    const float* __restrict__ img, int gr, int tx, float* __restrict__ w)
{
    gr = (gr < 0) ? 1 : ((gr > HH - 1) ? (2 * HH - 2 - gr) : gr);
    const float* rowp = img + gr * WW;
    const float4 q = __ldg((const float4*)rowp + tx);
    w[1] = q.x; w[2] = q.y; w[3] = q.z; w[4] = q.w;
    w[0] = (tx == 0)      ? q.y : __ldg(rowp + 4 * tx - 1);
    w[5] = (tx == WW/4-1) ? q.z : __ldg(rowp + 4 * tx + 4);
}

__global__ __launch_bounds__(256) void EKG_conv_kernel(
    const float* __restrict__ Fd,
    float* __restrict__ out)
{
    const int bc   = blockIdx.y;
    const int tid  = threadIdx.x;
    const int tx   = tid & 63;
    const int ty   = tid >> 6;
    const int rbase = blockIdx.x * ROWS_PER_BLOCK + ty * ROWS_PER_THREAD;

    const float* __restrict__ img = Fd  + (size_t)bc * IMG_PIX;
    float*       __restrict__ o   = out + (size_t)bc * IMG_PIX;

    const float* kwp = g_kw + bc * 9;
    const float w00 = __ldg(kwp+0), w01 = __ldg(kwp+1), w02 = __ldg(kwp+2);
    const float w10 = __ldg(kwp+3), w11 = __ldg(kwp+4), w12 = __ldg(kwp+5);
    const float w20 = __ldg(kwp+6), w21 = __ldg(kwp+7), w22 = __ldg(kwp+8);

    float win[3][6];
    load_row6(img, rbase - 1, tx, win[0]);
    load_row6(img, rbase + 0, tx, win[1]);

    #pragma unroll
    for (int rr = 0; rr < ROWS_PER_THREAD; ++rr) {
        load_row6(img, rbase + rr + 1, tx, win[(rr + 2) % 3]);

        const float* T  = win[rr % 3];
        const float* M  = win[(rr + 1) % 3];
        const float* Bt = win[(rr + 2) % 3];

        float4 r;
        r.x = w00*T[0]; r.x = fmaf(w01,T[1],r.x); r.x = fmaf(w02,T[2],r.x);
        r.x = fmaf(w10,M[0],r.x); r.x = fmaf(w11,M[1],r.x); r.x = fmaf(w12,M[2],r.x);
        r.x = fmaf(w20,Bt[0],r.x); r.x = fmaf(w21,Bt[1],r.x); r.x = fmaf(w22,Bt[2],r.x);

        r.y = w00*T[1]; r.y = fmaf(w01,T[2],r.y); r.y = fmaf(w02,T[3],r.y);
        r.y = fmaf(w10,M[1],r.y); r.y = fmaf(w11,M[2],r.y); r.y = fmaf(w12,M[3],r.y);
        r.y = fmaf(w20,Bt[1],r.y); r.y = fmaf(w21,Bt[2],r.y); r.y = fmaf(w22,Bt[3],r.y);

        r.z = w00*T[2]; r.z = fmaf(w01,T[3],r.z); r.z = fmaf(w02,T[4],r.z);
        r.z = fmaf(w10,M[2],r.z); r.z = fmaf(w11,M[3],r.z); r.z = fmaf(w12,M[4],r.z);
        r.z = fmaf(w20,Bt[2],r.z); r.z = fmaf(w21,Bt[3],r.z); r.z = fmaf(w22,Bt[4],r.z);

        r.w = w00*T[3]; r.w = fmaf(w01,T[4],r.w); r.w = fmaf(w02,T[5],r.w);
        r.w = fmaf(w10,M[3],r.w); r.w = fmaf(w11,M[4],r.w); r.w = fmaf(w12,M[5],r.w);
        r.w = fmaf(w20,Bt[3],r.w); r.w = fmaf(w21,Bt[4],r.w); r.w = fmaf(w22,Bt[5],r.w);

        __stcs((float4*)(o + (size_t)(rbase + rr) * WW + 4 * tx), r);
    }
}

// ---------------------------------------------------------------------------
extern "C" void kernel_launch(void* const* d_in, const int* in_sizes, int n_in,
                              void* d_out, int out_size) {
    const float* Fd = (const float*)d_in[0];
    const float* Fc = (const float*)d_in[1];
    const float* W1 = (const float*)d_in[2];
    const float* b1 = (const float*)d_in[3];
    const float* W2 = (const float*)d_in[4];
    const float* b2 = (const float*)d_in[5];
    float* out = (float*)d_out;

    const int write_tail = ((size_t)out_size >= FOUT_ELEMS + (size_t)B_SZ * CKK) ? 1 : 0;
    float* kw_tail = out + FOUT_ELEMS;

    EKG_mlp1<<<dim3(3, 16), 192>>>(Fc, W1, b1);
    EKG_mlp2<<<dim3(3, 18), 192>>>(W2, b2);
    EKG_softmax<<<B_SZ, CKK>>>(kw_tail, write_tail);

    dim3 grid(HH / ROWS_PER_BLOCK, N_IMG);
    EKG_conv_kernel<<<grid, 256>>>(Fd, out);
}

// round 16
// speedup vs baseline: 1.2277x; 1.0209x over previous
#include <cuda_runtime.h>
#include <cuda_bf16.h>
#include <math.h>

#define B_SZ   16
#define C_IN   64
#define HH     256
#define WW     256
#define CKK    576
#define FC_DIM 512
#define IMG_PIX (HH * WW)
#define N_IMG  (B_SZ * C_IN)
#define FOUT_ELEMS ((size_t)N_IMG * IMG_PIX)

// Partials (deterministic fixed-order summation)
__device__ float g_p1[32][B_SZ * CKK];  // layer1 partials per 16-i-chunk (ic0 includes b1)
__device__ float g_p2[36][B_SZ * CKK];  // layer2 partials per 16-i-chunk (ic0 includes b2)
__device__ float g_kw[B_SZ * CKK];      // softmaxed kernel weights

// ---------------------------------------------------------------------------
// Layer 1: 96 blocks = (jt 0..2) x (ic 0..31). Block: 192 threads.
// Tile W1 [16 x 192] (12KB smem, 4 float4 loads/thread) + Fc slice [16 x 16].
// ---------------------------------------------------------------------------
__global__ __launch_bounds__(192) void EKG_mlp1(
    const float* __restrict__ Fc,
    const float* __restrict__ W1, const float* __restrict__ b1)
{
    __shared__ float sw[16 * 192];    // 12KB weight tile
    __shared__ float sfc[16 * 16];    // 1KB input slice

    const int jt = blockIdx.x;        // 0..2
    const int ic = blockIdx.y;        // 0..31
    const int i0 = ic * 16;
    const int tid = threadIdx.x;
    const int j  = jt * 192 + tid;

    {
        const float4* __restrict__ W1_4 = (const float4*)W1;
        float4* sw4 = (float4*)sw;
        #pragma unroll
        for (int q = tid; q < 16 * 48; q += 192) {
            const int r = q / 48, c = q % 48;
            sw4[r * 48 + c] = __ldg(W1_4 + (size_t)(i0 + r) * (CKK / 4) + jt * 48 + c);
        }
    }
    if (tid < 64) {
        const float4* __restrict__ Fc4 = (const float4*)Fc;
        float4* sfc4 = (float4*)sfc;
        const int b = tid >> 2, c = tid & 3;
        sfc4[b * 4 + c] = __ldg(Fc4 + b * (FC_DIM / 4) + ic * 4 + c);
    }
    __syncthreads();

    float acc[16];
    #pragma unroll
    for (int b = 0; b < 16; ++b) acc[b] = 0.f;
    #pragma unroll
    for (int il = 0; il < 16; ++il) {
        const float w = sw[il * 192 + tid];
        #pragma unroll
        for (int b = 0; b < 16; ++b)
            acc[b] = fmaf(sfc[b * 16 + il], w, acc[b]);
    }

    const float bias = (ic == 0) ? b1[j] : 0.0f;
    #pragma unroll
    for (int b = 0; b < 16; ++b)
        g_p1[ic][b * CKK + j] = acc[b] + bias;
}

// ---------------------------------------------------------------------------
// Layer 2: 108 blocks = (jt 0..2) x (ic 0..35). Same structure over W2.
// Input h = relu(sum of 32 layer-1 partials), fixed-order tree.
// ---------------------------------------------------------------------------
__global__ __launch_bounds__(192) void EKG_mlp2(
    const float* __restrict__ W2, const float* __restrict__ b2)
{
    __shared__ float sw[16 * 192];
    __shared__ float sfc[16 * 16];

    const int jt = blockIdx.x;        // 0..2
    const int ic = blockIdx.y;        // 0..35
    const int i0 = ic * 16;
    const int tid = threadIdx.x;
    const int j  = jt * 192 + tid;

    {
        const float4* __restrict__ W2_4 = (const float4*)W2;
        float4* sw4 = (float4*)sw;
        #pragma unroll
        for (int q = tid; q < 16 * 48; q += 192) {
            const int r = q / 48, c = q % 48;
            sw4[r * 48 + c] = __ldg(W2_4 + (size_t)(i0 + r) * (CKK / 4) + jt * 48 + c);
        }
    }
    // h slice [16 x 16] = relu(sum of 32 partials), fixed order
    #pragma unroll
    for (int q = tid; q < 256; q += 192) {
        const int b = q >> 4, il = q & 15;
        const int idx = b * CKK + i0 + il;
        float s0 = 0.f, s1 = 0.f, s2 = 0.f, s3 = 0.f;
        #pragma unroll
        for (int t = 0; t < 8; ++t) {
            s0 += g_p1[t][idx];
            s1 += g_p1[8 + t][idx];
            s2 += g_p1[16 + t][idx];
            s3 += g_p1[24 + t][idx];
        }
        sfc[q] = fmaxf((s0 + s1) + (s2 + s3), 0.0f);
    }
    __syncthreads();

    float acc[16];
    #pragma unroll
    for (int b = 0; b < 16; ++b) acc[b] = 0.f;
    #pragma unroll
    for (int il = 0; il < 16; ++il) {
        const float w = sw[il * 192 + tid];
        #pragma unroll
        for (int b = 0; b < 16; ++b)
            acc[b] = fmaf(sfc[b * 16 + il], w, acc[b]);
    }

    const float bias = (ic == 0) ? b2[j] : 0.0f;
    #pragma unroll
    for (int b = 0; b < 16; ++b)
        g_p2[ic][b * CKK + j] = acc[b] + bias;
}

// ---------------------------------------------------------------------------
// Softmax over 576 (summing the 36 logit partials). grid 16, block 576.
// ---------------------------------------------------------------------------
__global__ __launch_bounds__(CKK) void EKG_softmax(
    float* __restrict__ kw_tail, int write_tail)
{
    __shared__ float red[32];
    __shared__ float bcast;
    const int b = blockIdx.x;
    const int j = threadIdx.x;
    const int lane = j & 31;
    const int wid  = j >> 5;
    const int idx  = b * CKK + j;

    float s0 = 0.f, s1 = 0.f, s2 = 0.f, s3 = 0.f;
    #pragma unroll
    for (int t = 0; t < 9; ++t) {
        s0 += g_p2[t][idx];
        s1 += g_p2[9 + t][idx];
        s2 += g_p2[18 + t][idx];
        s3 += g_p2[27 + t][idx];
    }
    const float logit = (s0 + s1) + (s2 + s3);

    float m = logit;
    #pragma unroll
    for (int o = 16; o > 0; o >>= 1)
        m = fmaxf(m, __shfl_xor_sync(0xffffffffu, m, o));
    if (lane == 0) red[wid] = m;
    __syncthreads();
    if (wid == 0) {
        float v = (lane < 18) ? red[lane] : -INFINITY;
        #pragma unroll
        for (int o = 16; o > 0; o >>= 1)
            v = fmaxf(v, __shfl_xor_sync(0xffffffffu, v, o));
        if (lane == 0) bcast = v;
    }
    __syncthreads();
    const float e = expf(logit - bcast);

    float s = e;
    #pragma unroll
    for (int o = 16; o > 0; o >>= 1)
        s += __shfl_xor_sync(0xffffffffu, s, o);
    __syncthreads();
    if (lane == 0) red[wid] = s;
    __syncthreads();
    if (wid == 0) {
        float v = (lane < 18) ? red[lane] : 0.0f;
        #pragma unroll
        for (int o = 16; o > 0; o >>= 1)
            v += __shfl_xor_sync(0xffffffffu, v, o);
        if (lane == 0) bcast = v;
    }
    __syncthreads();

    const float kw = e / bcast;
    g_kw[idx] = kw;
    if (write_tail) kw_tail[idx] = kw;
}

// ---------------------------------------------------------------------------
// Depthwise 3x3 conv, reflect pad, no smem (measured-best, unchanged).
// Block 256: tx 0..63 (float4 col group), ty 0..3 (8-row strip). Grid (8,1024).
// ---------------------------------------------------------------------------
#define ROWS_PER_BLOCK 32
#define ROWS_PER_THREAD 8

__device__ __forceinline__ void load_row6(
    const float* __restrict__ img, int gr, int tx, float* __restrict__ w)
{
    gr = (gr < 0) ? 1 : ((gr > HH - 1) ? (2 * HH - 2 - gr) : gr);
    const float* rowp = img + gr * WW;
    const float4 q = __ldg((const float4*)rowp + tx);
    w[1] = q.x; w[2] = q.y; w[3] = q.z; w[4] = q.w;
    w[0] = (tx == 0)      ? q.y : __ldg(rowp + 4 * tx - 1);
    w[5] = (tx == WW/4-1) ? q.z : __ldg(rowp + 4 * tx + 4);
}

__global__ __launch_bounds__(256) void EKG_conv_kernel(
    const float* __restrict__ Fd,
    float* __restrict__ out)
{
    const int bc   = blockIdx.y;
    const int tid  = threadIdx.x;
    const int tx   = tid & 63;
    const int ty   = tid >> 6;
    const int rbase = blockIdx.x * ROWS_PER_BLOCK + ty * ROWS_PER_THREAD;

    const float* __restrict__ img = Fd  + (size_t)bc * IMG_PIX;
    float*       __restrict__ o   = out + (size_t)bc * IMG_PIX;

    const float* kwp = g_kw + bc * 9;
    const float w00 = __ldg(kwp+0), w01 = __ldg(kwp+1), w02 = __ldg(kwp+2);
    const float w10 = __ldg(kwp+3), w11 = __ldg(kwp+4), w12 = __ldg(kwp+5);
    const float w20 = __ldg(kwp+6), w21 = __ldg(kwp+7), w22 = __ldg(kwp+8);

    float win[3][6];
    load_row6(img, rbase - 1, tx, win[0]);
    load_row6(img, rbase + 0, tx, win[1]);

    #pragma unroll
    for (int rr = 0; rr < ROWS_PER_THREAD; ++rr) {
        load_row6(img, rbase + rr + 1, tx, win[(rr + 2) % 3]);

        const float* T  = win[rr % 3];
        const float* M  = win[(rr + 1) % 3];
        const float* Bt = win[(rr + 2) % 3];

        float4 r;
        r.x = w00*T[0]; r.x = fmaf(w01,T[1],r.x); r.x = fmaf(w02,T[2],r.x);
        r.x = fmaf(w10,M[0],r.x); r.x = fmaf(w11,M[1],r.x); r.x = fmaf(w12,M[2],r.x);
        r.x = fmaf(w20,Bt[0],r.x); r.x = fmaf(w21,Bt[1],r.x); r.x = fmaf(w22,Bt[2],r.x);

        r.y = w00*T[1]; r.y = fmaf(w01,T[2],r.y); r.y = fmaf(w02,T[3],r.y);
        r.y = fmaf(w10,M[1],r.y); r.y = fmaf(w11,M[2],r.y); r.y = fmaf(w12,M[3],r.y);
        r.y = fmaf(w20,Bt[1],r.y); r.y = fmaf(w21,Bt[2],r.y); r.y = fmaf(w22,Bt[3],r.y);

        r.z = w00*T[2]; r.z = fmaf(w01,T[3],r.z); r.z = fmaf(w02,T[4],r.z);
        r.z = fmaf(w10,M[2],r.z); r.z = fmaf(w11,M[3],r.z); r.z = fmaf(w12,M[4],r.z);
        r.z = fmaf(w20,Bt[2],r.z); r.z = fmaf(w21,Bt[3],r.z); r.z = fmaf(w22,Bt[4],r.z);

        r.w = w00*T[3]; r.w = fmaf(w01,T[4],r.w); r.w = fmaf(w02,T[5],r.w);
        r.w = fmaf(w10,M[3],r.w); r.w = fmaf(w11,M[4],r.w); r.w = fmaf(w12,M[5],r.w);
        r.w = fmaf(w20,Bt[3],r.w); r.w = fmaf(w21,Bt[4],r.w); r.w = fmaf(w22,Bt[5],r.w);

        __stcs((float4*)(o + (size_t)(rbase + rr) * WW + 4 * tx), r);
    }
}

// ---------------------------------------------------------------------------
extern "C" void kernel_launch(void* const* d_in, const int* in_sizes, int n_in,
                              void* d_out, int out_size) {
    const float* Fd = (const float*)d_in[0];
    const float* Fc = (const float*)d_in[1];
    const float* W1 = (const float*)d_in[2];
    const float* b1 = (const float*)d_in[3];
    const float* W2 = (const float*)d_in[4];
    const float* b2 = (const float*)d_in[5];
    float* out = (float*)d_out;

    const int write_tail = ((size_t)out_size >= FOUT_ELEMS + (size_t)B_SZ * CKK) ? 1 : 0;
    float* kw_tail = out + FOUT_ELEMS;

    EKG_mlp1<<<dim3(3, 32), 192>>>(Fc, W1, b1);
    EKG_mlp2<<<dim3(3, 36), 192>>>(W2, b2);
    EKG_softmax<<<B_SZ, CKK>>>(kw_tail, write_tail);

    dim3 grid(HH / ROWS_PER_BLOCK, N_IMG);
    EKG_conv_kernel<<<grid, 256>>>(Fd, out);
}